// round 4
// baseline (speedup 1.0000x reference)
#include <cuda_runtime.h>
#include <cuda_bf16.h>
#include <math_constants.h>

// Problem constants
#define BB 64
#define DD 8732
#define CC 21
#define BD (BB*DD)          // 558848
#define NEG_FACTOR 3
#define NBUCK 65536

// ---------------- device scratch (no allocation allowed) ----------------
__device__ float        g_cand[BD];
__device__ unsigned int g_hist1[NBUCK];
__device__ unsigned int g_hist2[NBUCK];
__device__ float        g_pos_sum;
__device__ float        g_neg_sum;
__device__ unsigned int g_npos;
__device__ int          g_T1;        // -1 => select everything positive
__device__ unsigned int g_need1;
__device__ unsigned int g_thr_bits;  // exclusive threshold (bits > thr summed)
__device__ unsigned int g_rem;       // count of tied-at-threshold values to add
__device__ unsigned int g_is_bytes;  // 1 if pos_indicator is a 1-byte bool array

// ---------------- zero scratch ----------------
__global__ void zero_kernel() {
    int i = blockIdx.x * blockDim.x + threadIdx.x;
    int stride = gridDim.x * blockDim.x;
    for (int j = i; j < NBUCK; j += stride) { g_hist1[j] = 0u; g_hist2[j] = 0u; }
    if (i == 0) {
        g_pos_sum = 0.f; g_neg_sum = 0.f; g_npos = 0u;
        g_T1 = -1; g_need1 = 0u; g_thr_bits = 0u; g_rem = 0u;
        g_is_bytes = 0u;
    }
}

// ---------------- dtype sniffer for pos_indicator ----------------
// Reads the buffer as BD/4 int words (in-bounds for both bool[BD] and int[BD]).
// An int32 0/1 array has every word in {0,1}. A packed-bool byte array with
// ~2% density will (w.p. ~1) contain a word with a set byte above byte 0
// (values 256/65536/16777216/...), which cannot appear in the int32 case.
__global__ void detect_kernel(const int* __restrict__ posw) {
    int i = blockIdx.x * blockDim.x + threadIdx.x;
    int stride = gridDim.x * blockDim.x;
    bool bad = false;
    for (int j = i; j < BD / 4; j += stride) {
        unsigned int w = (unsigned int)posw[j];
        if (w > 1u) bad = true;
    }
    if (__syncthreads_or(bad) && threadIdx.x == 0) atomicOr(&g_is_bytes, 1u);
}

// ---------------- main compute: lse per box, pos sum, candidates, hist1 ----------------
__global__ void compute_kernel(const float* __restrict__ pred,
                               const float* __restrict__ gts,
                               const void* __restrict__ posv) {
    int i = blockIdx.x * blockDim.x + threadIdx.x;
    float my_pos = 0.f;
    unsigned int my_n = 0u;

    const unsigned int is_bytes = g_is_bytes;

    if (i < BD) {
        const float* x = pred + (size_t)i * CC;
        float xs[CC];
        float m = -CUDART_INF_F;
#pragma unroll
        for (int c = 0; c < CC; c++) { xs[c] = x[c]; m = fmaxf(m, xs[c]); }
        float s = 0.f;
#pragma unroll
        for (int c = 0; c < CC; c++) s += __expf(xs[c] - m);
        float lse = m + __logf(s);

        bool p;
        if (is_bytes) p = (((const unsigned char*)posv)[i] != 0);
        else          p = (((const int*)posv)[i] != 0);

        float val = 0.f;
        if (p) {
            const float* g = gts + (size_t)i * CC;
            float dot = 0.f;
#pragma unroll
            for (int c = 0; c < CC; c++) dot += g[c] * xs[c];
            my_pos = lse - dot;   // one-hot: sum_c g[c]*(lse - x[c]) = lse - x_label
            my_n = 1u;
        } else {
            float gbg = gts[(size_t)i * CC + (CC - 1)];  // one-hot: 0 or 1
            val = gbg * (lse - xs[CC - 1]);              // >= 0
        }
        g_cand[i] = val;
        if (val > 0.f) atomicAdd(&g_hist1[__float_as_uint(val) >> 16], 1u);
    }

    // block reduce pos_sum / npos
    __shared__ float sf[256];
    __shared__ unsigned int si[256];
    int t = threadIdx.x;
    sf[t] = my_pos; si[t] = my_n;
    __syncthreads();
    for (int off = 128; off > 0; off >>= 1) {
        if (t < off) { sf[t] += sf[t + off]; si[t] += si[t + off]; }
        __syncthreads();
    }
    if (t == 0) {
        if (sf[0] != 0.f) atomicAdd(&g_pos_sum, sf[0]);
        if (si[0] != 0u)  atomicAdd(&g_npos, si[0]);
    }
}

// ---------------- radix-select scan over a 65536-bucket histogram ----------------
// level==1: find top-16-bit bucket T1 and remaining need within it.
// level==2: find low-16-bit bucket T2 -> exact threshold bits + tie count.
__global__ void scan_kernel(int level) {
    __shared__ unsigned int part[1024];
    int t = threadIdx.x;

    const unsigned int* hist;
    unsigned int k;
    if (level == 1) {
        hist = g_hist1;
        unsigned long long N = (unsigned long long)g_npos;
        unsigned long long k3 = 3ull * N;
        unsigned long long kn = (unsigned long long)BD - N;
        k = (unsigned int)(k3 < kn ? k3 : kn);
    } else {
        if (g_T1 < 0) return;     // thr_bits stays 0, rem 0 => sum all positives
        hist = g_hist2;
        k = g_need1;              // guaranteed 1..count(T1)
    }

    unsigned int s = 0;
    int base = t * 64;
#pragma unroll 8
    for (int j = 0; j < 64; j++) s += hist[base + j];
    part[t] = s;
    __syncthreads();

    // inclusive suffix scan: part[t] = count of values in buckets >= t*64
    for (int off = 1; off < 1024; off <<= 1) {
        unsigned int v = (t + off < 1024) ? part[t + off] : 0u;
        __syncthreads();
        part[t] += v;
        __syncthreads();
    }

    unsigned int total = part[0];
    if (level == 1 && t == 0 && (k == 0u || total < k)) {
        g_T1 = -1; g_need1 = 0u;   // fewer positive candidates than k: take them all
    }
    if (k == 0u || total < k) return;

    unsigned int above = (t < 1023) ? part[t + 1] : 0u;
    bool owner = (part[t] >= k) && (above < k);
    if (owner) {
        unsigned int cum = above;
        int T = -1; unsigned int need = 0u;
        for (int b = base + 63; b >= base; b--) {
            unsigned int h = hist[b];
            if (cum + h >= k) { T = b; need = k - cum; break; }
            cum += h;
        }
        if (level == 1) { g_T1 = T; g_need1 = need; }
        else {
            // all values in low-bucket T of high-bucket T1 share one 32-bit pattern
            g_thr_bits = (((unsigned int)g_T1) << 16) | (unsigned int)T;
            g_rem = need;
        }
    }
}

// ---------------- build low-16-bit histogram for the boundary bucket ----------------
__global__ void hist2_kernel() {
    int T1 = g_T1;
    if (T1 < 0) return;
    int i = blockIdx.x * blockDim.x + threadIdx.x;
    if (i >= BD) return;
    float v = g_cand[i];
    if (v > 0.f) {
        unsigned int b = __float_as_uint(v);
        if ((int)(b >> 16) == T1) atomicAdd(&g_hist2[b & 0xffffu], 1u);
    }
}

// ---------------- sum all candidates strictly above the threshold ----------------
__global__ void negsum_kernel() {
    unsigned int thr = g_thr_bits;
    int i = blockIdx.x * blockDim.x + threadIdx.x;
    float local = 0.f;
    if (i < BD) {
        float v = g_cand[i];
        if (v > 0.f && __float_as_uint(v) > thr) local = v;
    }
    __shared__ float sf[256];
    int t = threadIdx.x;
    sf[t] = local;
    __syncthreads();
    for (int off = 128; off > 0; off >>= 1) {
        if (t < off) sf[t] += sf[t + off];
        __syncthreads();
    }
    if (t == 0 && sf[0] != 0.f) atomicAdd(&g_neg_sum, sf[0]);
}

// ---------------- finalize ----------------
__global__ void final_kernel(float* __restrict__ out) {
    float thrv = __uint_as_float(g_thr_bits);
    float neg = g_neg_sum + (float)g_rem * thrv;
    out[0] = (g_pos_sum + neg) / (float)g_npos;
}

extern "C" void kernel_launch(void* const* d_in, const int* in_sizes, int n_in,
                              void* d_out, int out_size) {
    const float* pred = (const float*)d_in[0];
    const float* gts  = (const float*)d_in[1];
    const void*  pos  = d_in[2];
    float* out = (float*)d_out;

    const int T = 256;
    const int G = (BD + T - 1) / T;

    zero_kernel<<<64, 512>>>();
    detect_kernel<<<64, 256>>>((const int*)pos);
    compute_kernel<<<G, T>>>(pred, gts, pos);
    scan_kernel<<<1, 1024>>>(1);
    hist2_kernel<<<G, T>>>();
    scan_kernel<<<1, 1024>>>(2);
    negsum_kernel<<<G, T>>>();
    final_kernel<<<1, 1>>>(out);
}

// round 7
// speedup vs baseline: 2.0942x; 2.0942x over previous
#include <cuda_runtime.h>
#include <math_constants.h>

// Problem constants
#define BB 64
#define DD 8732
#define CC 21
#define BD (BB*DD)            // 558848
#define NBUCK 65536
#define CHUNKS 1024           // 64 buckets per chunk
#define CMP_T 256
#define CMP_G (BD/CMP_T)      // 2183 exactly (558848 = 2183*256)
#define ROW_FLOATS (CMP_T*CC) // 5376
#define ROW_VEC4 (ROW_FLOATS/4) // 1344
#define VG ((BD/4 + 255)/256) // 546 blocks for vec4 passes

// ---------------- device scratch (no allocation allowed) ----------------
__device__ float        g_cand[BD];
__device__ unsigned int g_hist1[NBUCK];
__device__ unsigned int g_hist2[NBUCK];
__device__ unsigned int g_chunk1[CHUNKS];
__device__ unsigned int g_chunk2[CHUNKS];
__device__ float        g_pos_sum;
__device__ float        g_neg_sum;
__device__ unsigned int g_npos;
__device__ int          g_T1;        // -1 => take every positive candidate
__device__ unsigned int g_need1;
__device__ unsigned int g_thr_bits;  // exclusive threshold (bits > thr summed)
__device__ unsigned int g_rem;       // tied-at-threshold count to add
__device__ unsigned int g_is_bytes;  // sticky dtype flag (deterministic per input)
__device__ unsigned int g_cnt1, g_cnt2, g_cnt3;

// ---------------- block-cooperative radix select (256 threads) ----------------
// hist: 65536 fine buckets; chunk: 1024 coarse sums (64 buckets each).
// Finds bucket T s.t. suffix-count crosses k. level 1 -> (g_T1, g_need1);
// level 2 -> (g_thr_bits, g_rem).
__device__ void radix_scan_block(const unsigned int* __restrict__ hist,
                                 const unsigned int* __restrict__ chunk,
                                 unsigned int k, int level)
{
    __shared__ unsigned int part[256];
    __shared__ unsigned int found[2];
    __shared__ unsigned int suf[128];
    int t = threadIdx.x;
    int base4 = t * 4;
    part[t] = chunk[base4] + chunk[base4 + 1] + chunk[base4 + 2] + chunk[base4 + 3];
    __syncthreads();
    // inclusive suffix scan over 256 segment sums
    for (int off = 1; off < 256; off <<= 1) {
        unsigned int v = (t + off < 256) ? part[t + off] : 0u;
        __syncthreads();
        part[t] += v;
        __syncthreads();
    }
    unsigned int total = part[0];
    if (k == 0u || total < k) {
        if (t == 0 && level == 1) { g_T1 = -1; g_need1 = 0u; }  // take all positives
        return;
    }
    // exactly one owner segment
    unsigned int above = (t < 255) ? part[t + 1] : 0u;
    if (part[t] >= k && above < k) {
        unsigned int cum = above;
        for (int cj = 3; cj >= 0; cj--) {
            unsigned int h = chunk[base4 + cj];
            if (cum + h >= k) { found[0] = (unsigned int)(base4 + cj); found[1] = k - cum; break; }
            cum += h;
        }
    }
    __syncthreads();
    unsigned int c = found[0], k2 = found[1];
    // suffix scan over the 64 fine buckets of chunk c (suf[64..127] stay 0)
    if (t < 128) suf[t] = (t < 64) ? hist[c * 64 + t] : 0u;
    __syncthreads();
    for (int off = 1; off < 64; off <<= 1) {
        unsigned int v = (t < 64) ? suf[t + off] : 0u;
        __syncthreads();
        if (t < 64) suf[t] += v;
        __syncthreads();
    }
    if (t < 64) {
        unsigned int ab = suf[t + 1 < 64 ? t + 1 : 64];  // suf[64]==0
        if (suf[t] >= k2 && ab < k2) {
            unsigned int T = c * 64 + (unsigned int)t;
            if (level == 1) { g_T1 = (int)T; g_need1 = k2 - ab; }
            else {
                g_thr_bits = (((unsigned int)g_T1) << 16) | T;
                g_rem = k2 - ab;
            }
        }
    }
}

// ---------------- zero scratch + pos_indicator dtype sniff (fused) ----------------
// Dtype sniff: read buffer as BD/4 int words (in-bounds for bool[BD] and int[BD]).
// int32 0/1 arrays have every word in {0,1}; a ~2%-dense byte-bool array w.p.~1
// contains a word with a byte set above byte 0 (256/65536/...), impossible for
// int32 0/1. g_is_bytes is sticky-OR: deterministic for a fixed input.
__global__ void zero_detect_kernel(const int* __restrict__ posw) {
    int i = blockIdx.x * blockDim.x + threadIdx.x;
    int stride = gridDim.x * blockDim.x;
    uint4 z = make_uint4(0u, 0u, 0u, 0u);
    for (int j = i; j < NBUCK / 4; j += stride) {
        ((uint4*)g_hist1)[j] = z;
        ((uint4*)g_hist2)[j] = z;
    }
    for (int j = i; j < CHUNKS; j += stride) { g_chunk1[j] = 0u; g_chunk2[j] = 0u; }
    bool bad = false;
    for (int j = i; j < BD / 4; j += stride) {
        if ((unsigned int)posw[j] > 1u) bad = true;
    }
    if (bad) atomicOr(&g_is_bytes, 1u);
    if (i == 0) {
        g_pos_sum = 0.f; g_neg_sum = 0.f; g_npos = 0u;
        g_T1 = -1; g_need1 = 0u; g_thr_bits = 0u; g_rem = 0u;
        g_cnt1 = 0u; g_cnt2 = 0u; g_cnt3 = 0u;
    }
}

// ---------------- main compute + fused level-1 select in last block ----------------
__global__ void __launch_bounds__(CMP_T) compute_kernel(
        const float* __restrict__ pred,
        const float* __restrict__ gts,
        const void* __restrict__ posv)
{
    __shared__ float4 tile4[ROW_VEC4];  // 21504 B staged predicts tile
    float* tile = (float*)tile4;
    int t = threadIdx.x;
    int blk = blockIdx.x;

    // coalesced float4 load of this block's 256 rows (byte offset blk*21504, 16B aligned)
    const float4* src = ((const float4*)pred) + (size_t)blk * ROW_VEC4;
#pragma unroll
    for (int j = 0; j < 5; j++) tile4[t + j * CMP_T] = src[t + j * CMP_T];
    if (t < ROW_VEC4 - 5 * CMP_T) tile4[5 * CMP_T + t] = src[5 * CMP_T + t];
    __syncthreads();

    int i = blk * CMP_T + t;
    const float* x = tile + t * CC;   // stride 21: conflict-free (21 coprime 32)
    float xs[CC];
    float m = -CUDART_INF_F;
#pragma unroll
    for (int c = 0; c < CC; c++) { xs[c] = x[c]; m = fmaxf(m, xs[c]); }
    float s = 0.f;
#pragma unroll
    for (int c = 0; c < CC; c++) s += __expf(xs[c] - m);
    float lse = m + __logf(s);

    bool p = g_is_bytes ? (((const unsigned char*)posv)[i] != 0)
                        : (((const int*)posv)[i] != 0);

    float my_pos = 0.f;
    unsigned int my_n = 0u;
    float val = 0.f;
    if (p) {
        const float* g = gts + (size_t)i * CC;
        float dot = 0.f;
#pragma unroll
        for (int c = 0; c < CC; c++) dot += g[c] * xs[c];  // one-hot -> x[label]
        my_pos = lse - dot;
        my_n = 1u;
    } else {
        float gbg = __ldg(gts + (size_t)i * CC + (CC - 1));  // 0 or 1
        val = gbg * (lse - xs[CC - 1]);                      // >= 0
    }
    g_cand[i] = val;
    if (val > 0.f) {
        unsigned int b = __float_as_uint(val);
        atomicAdd(&g_hist1[b >> 16], 1u);
        atomicAdd(&g_chunk1[b >> 22], 1u);
    }

    // block reduce pos_sum / npos via shuffles
#pragma unroll
    for (int off = 16; off > 0; off >>= 1) {
        my_pos += __shfl_down_sync(0xffffffffu, my_pos, off);
        my_n   += __shfl_down_sync(0xffffffffu, my_n, off);
    }
    __shared__ float wf[8];
    __shared__ unsigned int wi[8];
    if ((t & 31) == 0) { wf[t >> 5] = my_pos; wi[t >> 5] = my_n; }
    __syncthreads();
    if (t < 32) {
        float v = (t < 8) ? wf[t] : 0.f;
        unsigned int n = (t < 8) ? wi[t] : 0u;
#pragma unroll
        for (int off = 4; off > 0; off >>= 1) {
            v += __shfl_down_sync(0xffffffffu, v, off);
            n += __shfl_down_sync(0xffffffffu, n, off);
        }
        if (t == 0) {
            if (v != 0.f) atomicAdd(&g_pos_sum, v);
            if (n != 0u)  atomicAdd(&g_npos, n);
        }
    }

    // last finishing block runs the level-1 select
    __threadfence();
    __shared__ unsigned int isLast;
    if (t == 0) isLast = (atomicAdd(&g_cnt1, 1u) == (unsigned int)gridDim.x - 1u) ? 1u : 0u;
    __syncthreads();
    if (isLast) {
        unsigned long long N = (unsigned long long)g_npos;
        unsigned long long k3 = 3ull * N;
        unsigned long long kn = (unsigned long long)BD - N;
        unsigned int k = (unsigned int)(k3 < kn ? k3 : kn);
        radix_scan_block(g_hist1, g_chunk1, k, 1);
    }
}

// ---------------- low-16 histogram of boundary bucket + fused level-2 select ----------------
__global__ void __launch_bounds__(256) hist2_kernel() {
    int T1 = g_T1;
    int i = blockIdx.x * blockDim.x + threadIdx.x;
    if (T1 >= 0 && i < BD / 4) {
        float4 v4 = ((const float4*)g_cand)[i];
        float vv[4] = {v4.x, v4.y, v4.z, v4.w};
#pragma unroll
        for (int j = 0; j < 4; j++) {
            if (vv[j] > 0.f) {
                unsigned int b = __float_as_uint(vv[j]);
                if ((int)(b >> 16) == T1) {
                    atomicAdd(&g_hist2[b & 0xffffu], 1u);
                    atomicAdd(&g_chunk2[(b & 0xffffu) >> 6], 1u);
                }
            }
        }
    }
    __threadfence();
    __shared__ unsigned int isLast;
    if (threadIdx.x == 0) isLast = (atomicAdd(&g_cnt2, 1u) == (unsigned int)gridDim.x - 1u) ? 1u : 0u;
    __syncthreads();
    if (isLast && g_T1 >= 0)
        radix_scan_block(g_hist2, g_chunk2, g_need1, 2);
}

// ---------------- sum above threshold + fused finalize ----------------
__global__ void __launch_bounds__(256) negsum_kernel(float* __restrict__ out) {
    unsigned int thr = g_thr_bits;
    int i = blockIdx.x * blockDim.x + threadIdx.x;
    float local = 0.f;
    if (i < BD / 4) {
        float4 v4 = ((const float4*)g_cand)[i];
        float vv[4] = {v4.x, v4.y, v4.z, v4.w};
#pragma unroll
        for (int j = 0; j < 4; j++) {
            if (vv[j] > 0.f && __float_as_uint(vv[j]) > thr) local += vv[j];
        }
    }
#pragma unroll
    for (int off = 16; off > 0; off >>= 1)
        local += __shfl_down_sync(0xffffffffu, local, off);
    __shared__ float wf[8];
    int t = threadIdx.x;
    if ((t & 31) == 0) wf[t >> 5] = local;
    __syncthreads();
    if (t < 32) {
        float v = (t < 8) ? wf[t] : 0.f;
#pragma unroll
        for (int off = 4; off > 0; off >>= 1)
            v += __shfl_down_sync(0xffffffffu, v, off);
        if (t == 0 && v != 0.f) atomicAdd(&g_neg_sum, v);
    }

    __threadfence();
    __shared__ unsigned int isLast;
    if (t == 0) isLast = (atomicAdd(&g_cnt3, 1u) == (unsigned int)gridDim.x - 1u) ? 1u : 0u;
    __syncthreads();
    if (isLast && t == 0) {
        float thrv = __uint_as_float(g_thr_bits);
        float neg = g_neg_sum + (float)g_rem * thrv;
        out[0] = (g_pos_sum + neg) / (float)g_npos;
    }
}

extern "C" void kernel_launch(void* const* d_in, const int* in_sizes, int n_in,
                              void* d_out, int out_size) {
    const float* pred = (const float*)d_in[0];
    const float* gts  = (const float*)d_in[1];
    const void*  pos  = d_in[2];
    float* out = (float*)d_out;

    zero_detect_kernel<<<296, 256>>>((const int*)pos);
    compute_kernel<<<CMP_G, CMP_T>>>(pred, gts, pos);
    hist2_kernel<<<VG, 256>>>();
    negsum_kernel<<<VG, 256>>>(out);
}

// round 10
// speedup vs baseline: 2.1249x; 1.0146x over previous
#include <cuda_runtime.h>
#include <math_constants.h>

// Problem constants
#define BB 64
#define DD 8732
#define CC 21
#define BD (BB*DD)            // 558848
#define NBUCK 65536
#define CHUNKS 1024           // 64 buckets per chunk
#define CMP_T 256
#define CMP_G (BD/CMP_T)      // 2183 exactly (558848 = 2183*256)
#define ROW_FLOATS (CMP_T*CC) // 5376
#define ROW_VEC4 (ROW_FLOATS/4) // 1344

// ---------------- device scratch (no allocation allowed) ----------------
__device__ float        g_cmp[BD];        // compacted positive candidates
__device__ unsigned int g_hist1[NBUCK];
__device__ unsigned int g_hist2[NBUCK];
__device__ unsigned int g_chunk1[CHUNKS];
__device__ unsigned int g_chunk2[CHUNKS];
__device__ float        g_pos_sum;
__device__ unsigned int g_npos;
__device__ unsigned int g_ncand;
__device__ int          g_T1;        // -1 => take every positive candidate
__device__ unsigned int g_need1;
__device__ unsigned int g_thr_bits;  // exclusive threshold (bits > thr summed)
__device__ unsigned int g_rem;       // tied-at-threshold count to add
__device__ unsigned int g_is_bytes;  // sticky dtype flag (deterministic per input)
__device__ unsigned int g_cnt1;

// ---------------- level-1 radix select, 256-thread block ----------------
__device__ void radix_scan_256(const unsigned int* __restrict__ hist,
                               const unsigned int* __restrict__ chunk,
                               unsigned int k)
{
    __shared__ unsigned int part[256];
    __shared__ unsigned int found[2];
    __shared__ unsigned int suf[128];
    int t = threadIdx.x;
    int base4 = t * 4;
    part[t] = chunk[base4] + chunk[base4 + 1] + chunk[base4 + 2] + chunk[base4 + 3];
    __syncthreads();
    for (int off = 1; off < 256; off <<= 1) {
        unsigned int v = (t + off < 256) ? part[t + off] : 0u;
        __syncthreads();
        part[t] += v;
        __syncthreads();
    }
    unsigned int total = part[0];
    if (k == 0u || total < k) {
        if (t == 0) { g_T1 = -1; g_need1 = 0u; }  // take all positives
        return;
    }
    unsigned int above = (t < 255) ? part[t + 1] : 0u;
    if (part[t] >= k && above < k) {
        unsigned int cum = above;
        for (int cj = 3; cj >= 0; cj--) {
            unsigned int h = chunk[base4 + cj];
            if (cum + h >= k) { found[0] = (unsigned int)(base4 + cj); found[1] = k - cum; break; }
            cum += h;
        }
    }
    __syncthreads();
    unsigned int c = found[0], k2 = found[1];
    if (t < 128) suf[t] = (t < 64) ? hist[c * 64 + t] : 0u;
    __syncthreads();
    for (int off = 1; off < 64; off <<= 1) {
        unsigned int v = (t < 64) ? suf[t + off] : 0u;
        __syncthreads();
        if (t < 64) suf[t] += v;
        __syncthreads();
    }
    if (t < 64) {
        unsigned int ab = suf[t + 1 < 64 ? t + 1 : 64];
        if (suf[t] >= k2 && ab < k2) { g_T1 = (int)(c * 64 + t); g_need1 = k2 - ab; }
    }
}

// ---------------- level-2 radix select, 1024-thread block ----------------
__device__ void radix_scan_1024(const unsigned int* __restrict__ hist,
                                const unsigned int* __restrict__ chunk,
                                unsigned int k)
{
    __shared__ unsigned int part[1024];
    __shared__ unsigned int found[2];
    __shared__ unsigned int suf[128];
    int t = threadIdx.x;
    part[t] = chunk[t];
    __syncthreads();
    for (int off = 1; off < 1024; off <<= 1) {
        unsigned int v = (t + off < 1024) ? part[t + off] : 0u;
        __syncthreads();
        part[t] += v;
        __syncthreads();
    }
    // level 2 is only entered with k in [1, count(T1)], so a crossing exists
    unsigned int above = (t < 1023) ? part[t + 1] : 0u;
    if (part[t] >= k && above < k) { found[0] = (unsigned int)t; found[1] = k - above; }
    __syncthreads();
    unsigned int c = found[0], k2 = found[1];
    if (t < 128) suf[t] = (t < 64) ? hist[c * 64 + t] : 0u;
    __syncthreads();
    for (int off = 1; off < 64; off <<= 1) {
        unsigned int v = (t < 64) ? suf[t + off] : 0u;
        __syncthreads();
        if (t < 64) suf[t] += v;
        __syncthreads();
    }
    if (t < 64) {
        unsigned int ab = suf[t + 1 < 64 ? t + 1 : 64];
        if (suf[t] >= k2 && ab < k2) {
            g_thr_bits = (((unsigned int)g_T1) << 16) | (c * 64 + (unsigned int)t);
            g_rem = k2 - ab;
        }
    }
}

// ---------------- zero scratch + pos_indicator dtype sniff (fused) ----------------
// int32 0/1 arrays have every 32-bit word in {0,1}; a ~2%-dense byte-bool array
// w.p.~1 contains a word with a set byte above byte 0 (256/65536/...), which
// cannot occur for int32 0/1. g_is_bytes is sticky-OR: deterministic per input.
__global__ void zero_detect_kernel(const int* __restrict__ posw) {
    int i = blockIdx.x * blockDim.x + threadIdx.x;
    int stride = gridDim.x * blockDim.x;
    uint4 z = make_uint4(0u, 0u, 0u, 0u);
    for (int j = i; j < NBUCK / 4; j += stride) {
        ((uint4*)g_hist1)[j] = z;
        ((uint4*)g_hist2)[j] = z;
    }
    for (int j = i; j < CHUNKS; j += stride) { g_chunk1[j] = 0u; g_chunk2[j] = 0u; }
    bool bad = false;
    for (int j = i; j < BD / 4; j += stride) {
        if ((unsigned int)posw[j] > 1u) bad = true;
    }
    if (bad) atomicOr(&g_is_bytes, 1u);
    if (i == 0) {
        g_pos_sum = 0.f; g_npos = 0u; g_ncand = 0u;
        g_T1 = -1; g_need1 = 0u; g_thr_bits = 0u; g_rem = 0u;
        g_cnt1 = 0u;
    }
}

// ---------------- main compute + compaction + fused level-1 select ----------------
__global__ void __launch_bounds__(CMP_T) compute_kernel(
        const float* __restrict__ pred,
        const float* __restrict__ gts,
        const void* __restrict__ posv)
{
    __shared__ float4 tile4[ROW_VEC4];  // 21504 B staged predicts tile
    float* tile = (float*)tile4;
    int t = threadIdx.x;
    int blk = blockIdx.x;

    // coalesced float4 load of this block's 256 rows (blk*21504 B, 16B aligned)
    const float4* src = ((const float4*)pred) + (size_t)blk * ROW_VEC4;
#pragma unroll
    for (int j = 0; j < 5; j++) tile4[t + j * CMP_T] = src[t + j * CMP_T];
    if (t < ROW_VEC4 - 5 * CMP_T) tile4[5 * CMP_T + t] = src[5 * CMP_T + t];
    __syncthreads();

    int i = blk * CMP_T + t;
    const float* x = tile + t * CC;   // stride 21: conflict-free (21 coprime 32)
    float xs[CC];
    float m = -CUDART_INF_F;
#pragma unroll
    for (int c = 0; c < CC; c++) { xs[c] = x[c]; m = fmaxf(m, xs[c]); }
    float s = 0.f;
#pragma unroll
    for (int c = 0; c < CC; c++) s += __expf(xs[c] - m);
    float lse = m + __logf(s);

    bool p = g_is_bytes ? (((const unsigned char*)posv)[i] != 0)
                        : (((const int*)posv)[i] != 0);

    float my_pos = 0.f;
    unsigned int my_n = 0u;
    float val = 0.f;
    if (p) {
        const float* g = gts + (size_t)i * CC;
        float dot = 0.f;
#pragma unroll
        for (int c = 0; c < CC; c++) dot += g[c] * xs[c];  // one-hot -> x[label]
        my_pos = lse - dot;
        my_n = 1u;
    } else {
        float gbg = __ldg(gts + (size_t)i * CC + (CC - 1));  // 0 or 1
        val = gbg * (lse - xs[CC - 1]);                      // >= 0
    }

    // warp-aggregated compaction of positive candidates + histograms
    unsigned int mask = __ballot_sync(0xffffffffu, val > 0.f);
    if (val > 0.f) {
        int lane = t & 31;
        int leader = __ffs(mask) - 1;
        unsigned int pre = mask & ((1u << lane) - 1u);
        int base;
        if (lane == leader) base = (int)atomicAdd(&g_ncand, (unsigned int)__popc(mask));
        base = __shfl_sync(mask, base, leader);
        g_cmp[base + __popc(pre)] = val;

        unsigned int b = __float_as_uint(val);
        atomicAdd(&g_hist1[b >> 16], 1u);
        atomicAdd(&g_chunk1[b >> 22], 1u);
    }

    // block reduce pos_sum / npos via shuffles
#pragma unroll
    for (int off = 16; off > 0; off >>= 1) {
        my_pos += __shfl_down_sync(0xffffffffu, my_pos, off);
        my_n   += __shfl_down_sync(0xffffffffu, my_n, off);
    }
    __shared__ float wf[8];
    __shared__ unsigned int wi[8];
    if ((t & 31) == 0) { wf[t >> 5] = my_pos; wi[t >> 5] = my_n; }
    __syncthreads();
    if (t < 32) {
        float v = (t < 8) ? wf[t] : 0.f;
        unsigned int n = (t < 8) ? wi[t] : 0u;
#pragma unroll
        for (int off = 4; off > 0; off >>= 1) {
            v += __shfl_down_sync(0xffffffffu, v, off);
            n += __shfl_down_sync(0xffffffffu, n, off);
        }
        if (t == 0) {
            if (v != 0.f) atomicAdd(&g_pos_sum, v);
            if (n != 0u)  atomicAdd(&g_npos, n);
        }
    }

    // last finishing block runs the level-1 select
    __threadfence();
    __shared__ unsigned int isLast;
    if (t == 0) isLast = (atomicAdd(&g_cnt1, 1u) == (unsigned int)gridDim.x - 1u) ? 1u : 0u;
    __syncthreads();
    if (isLast) {
        unsigned long long N = (unsigned long long)g_npos;
        unsigned long long k3 = 3ull * N;
        unsigned long long kn = (unsigned long long)BD - N;
        unsigned int k = (unsigned int)(k3 < kn ? k3 : kn);
        radix_scan_256(g_hist1, g_chunk1, k);
    }
}

// ---------------- single-block tail: hist2 + scan2 + negsum + finalize ----------------
// Operates on the compacted candidate array (~26.6k floats, L2-resident).
__global__ void __launch_bounds__(1024) tail_kernel(float* __restrict__ out) {
    int t = threadIdx.x;
    int nc = (int)g_ncand;
    int T1 = g_T1;

    if (T1 >= 0) {
        // build low-16-bit histogram of the boundary bucket
        for (int j = t; j < nc; j += 1024) {
            float v = g_cmp[j];
            unsigned int b = __float_as_uint(v);
            if ((int)(b >> 16) == T1) {
                atomicAdd(&g_hist2[b & 0xffffu], 1u);
                atomicAdd(&g_chunk2[(b & 0xffffu) >> 6], 1u);
            }
        }
        __syncthreads();   // orders this block's global atomics before the scan reads
        radix_scan_1024(g_hist2, g_chunk2, g_need1);
        __syncthreads();
    }

    unsigned int thr = g_thr_bits;   // 0 when T1 < 0 -> sum every candidate
    float local = 0.f;
#pragma unroll 4
    for (int j = t; j < nc; j += 1024) {
        float v = g_cmp[j];                      // all compacted values are > 0
        if (__float_as_uint(v) > thr) local += v;
    }
#pragma unroll
    for (int off = 16; off > 0; off >>= 1)
        local += __shfl_down_sync(0xffffffffu, local, off);
    __shared__ float wf[32];
    if ((t & 31) == 0) wf[t >> 5] = local;
    __syncthreads();
    if (t < 32) {
        float v = wf[t];
#pragma unroll
        for (int off = 16; off > 0; off >>= 1)
            v += __shfl_down_sync(0xffffffffu, v, off);
        if (t == 0) {
            float thrv = __uint_as_float(g_thr_bits);
            float neg = v + (float)g_rem * thrv;
            out[0] = (g_pos_sum + neg) / (float)g_npos;
        }
    }
}

extern "C" void kernel_launch(void* const* d_in, const int* in_sizes, int n_in,
                              void* d_out, int out_size) {
    const float* pred = (const float*)d_in[0];
    const float* gts  = (const float*)d_in[1];
    const void*  pos  = d_in[2];
    float* out = (float*)d_out;

    zero_detect_kernel<<<296, 256>>>((const int*)pos);
    compute_kernel<<<CMP_G, CMP_T>>>(pred, gts, pos);
    tail_kernel<<<1, 1024>>>(out);
}

// round 11
// speedup vs baseline: 2.2134x; 1.0417x over previous
#include <cuda_runtime.h>
#include <math_constants.h>

// Problem constants
#define BB 64
#define DD 8732
#define CC 21
#define BD (BB*DD)            // 558848
#define NBUCK 65536
#define CHUNKS 1024           // 64 buckets per chunk
#define CMP_T 256
#define CMP_G (BD/CMP_T)      // 2183 exactly (558848 = 2183*256)
#define ROW_FLOATS (CMP_T*CC) // 5376
#define ROW_VEC4 (ROW_FLOATS/4) // 1344

// ---------------- device scratch (no allocation allowed) ----------------
// Zero-initialized at module load. The tail kernel scrubs everything it and
// compute touched back to zero, so every kernel_launch call (correctness run,
// each graph replay) starts from the same clean state. Deterministic.
__device__ float        g_cmp[BD];        // compacted positive candidates
__device__ unsigned int g_hist1[NBUCK];
__device__ unsigned int g_hist2[NBUCK];
__device__ unsigned int g_chunk1[CHUNKS];
__device__ unsigned int g_chunk2[CHUNKS];
__device__ float        g_pos_sum;
__device__ unsigned int g_npos;
__device__ unsigned int g_ncand;
__device__ int          g_T1;        // <0 => take every positive candidate (init 0 ok: see note)
__device__ unsigned int g_need1;
__device__ unsigned int g_thr_bits;  // exclusive threshold (bits > thr summed)
__device__ unsigned int g_rem;       // tied-at-threshold count to add
__device__ unsigned int g_cnt1;
// note: g_T1 is always written by compute's last block (radix_scan_256 writes
// either -1 or the found bucket) before tail reads it, so its initial value is
// irrelevant; tail still resets it for hygiene.

// ---------------- level-1 radix select, 256-thread block ----------------
__device__ void radix_scan_256(const unsigned int* __restrict__ hist,
                               const unsigned int* __restrict__ chunk,
                               unsigned int k)
{
    __shared__ unsigned int part[256];
    __shared__ unsigned int found[2];
    __shared__ unsigned int suf[128];
    int t = threadIdx.x;
    int base4 = t * 4;
    part[t] = chunk[base4] + chunk[base4 + 1] + chunk[base4 + 2] + chunk[base4 + 3];
    __syncthreads();
    for (int off = 1; off < 256; off <<= 1) {
        unsigned int v = (t + off < 256) ? part[t + off] : 0u;
        __syncthreads();
        part[t] += v;
        __syncthreads();
    }
    unsigned int total = part[0];
    if (k == 0u || total < k) {
        if (t == 0) { g_T1 = -1; g_need1 = 0u; }  // take all positives
        return;
    }
    unsigned int above = (t < 255) ? part[t + 1] : 0u;
    if (part[t] >= k && above < k) {
        unsigned int cum = above;
        for (int cj = 3; cj >= 0; cj--) {
            unsigned int h = chunk[base4 + cj];
            if (cum + h >= k) { found[0] = (unsigned int)(base4 + cj); found[1] = k - cum; break; }
            cum += h;
        }
    }
    __syncthreads();
    unsigned int c = found[0], k2 = found[1];
    if (t < 128) suf[t] = (t < 64) ? hist[c * 64 + t] : 0u;
    __syncthreads();
    for (int off = 1; off < 64; off <<= 1) {
        unsigned int v = (t < 64) ? suf[t + off] : 0u;
        __syncthreads();
        if (t < 64) suf[t] += v;
        __syncthreads();
    }
    if (t < 64) {
        unsigned int ab = suf[t + 1 < 64 ? t + 1 : 64];
        if (suf[t] >= k2 && ab < k2) { g_T1 = (int)(c * 64 + t); g_need1 = k2 - ab; }
    }
}

// ---------------- level-2 radix select, 1024-thread block ----------------
__device__ void radix_scan_1024(const unsigned int* __restrict__ hist,
                                const unsigned int* __restrict__ chunk,
                                unsigned int k)
{
    __shared__ unsigned int part[1024];
    __shared__ unsigned int found[2];
    __shared__ unsigned int suf[128];
    int t = threadIdx.x;
    part[t] = chunk[t];
    __syncthreads();
    for (int off = 1; off < 1024; off <<= 1) {
        unsigned int v = (t + off < 1024) ? part[t + off] : 0u;
        __syncthreads();
        part[t] += v;
        __syncthreads();
    }
    // level 2 is only entered with k in [1, count(T1)], so a crossing exists
    unsigned int above = (t < 1023) ? part[t + 1] : 0u;
    if (part[t] >= k && above < k) { found[0] = (unsigned int)t; found[1] = k - above; }
    __syncthreads();
    unsigned int c = found[0], k2 = found[1];
    if (t < 128) suf[t] = (t < 64) ? hist[c * 64 + t] : 0u;
    __syncthreads();
    for (int off = 1; off < 64; off <<= 1) {
        unsigned int v = (t < 64) ? suf[t + off] : 0u;
        __syncthreads();
        if (t < 64) suf[t] += v;
        __syncthreads();
    }
    if (t < 64) {
        unsigned int ab = suf[t + 1 < 64 ? t + 1 : 64];
        if (suf[t] >= k2 && ab < k2) {
            g_thr_bits = (((unsigned int)g_T1) << 16) | (c * 64 + (unsigned int)t);
            g_rem = k2 - ab;
        }
    }
}

// ---------------- main compute + compaction + fused level-1 select ----------------
__global__ void __launch_bounds__(CMP_T) compute_kernel(
        const float* __restrict__ pred,
        const float* __restrict__ gts,
        const int* __restrict__ pos)   // int32 0/1 (established in rounds 3->4)
{
    __shared__ float4 tile4[ROW_VEC4];  // 21504 B staged predicts tile
    float* tile = (float*)tile4;
    int t = threadIdx.x;
    int blk = blockIdx.x;
    int i = blk * CMP_T + t;

    // hoist the scattered per-box loads so their DRAM latency overlaps the
    // tile staging + softmax below
    int   p_raw = pos[i];
    float gbg   = __ldg(gts + (size_t)i * CC + (CC - 1));  // one-hot bg: 0 or 1

    // coalesced float4 load of this block's 256 rows (blk*21504 B, 16B aligned)
    const float4* src = ((const float4*)pred) + (size_t)blk * ROW_VEC4;
#pragma unroll
    for (int j = 0; j < 5; j++) tile4[t + j * CMP_T] = src[t + j * CMP_T];
    if (t < ROW_VEC4 - 5 * CMP_T) tile4[5 * CMP_T + t] = src[5 * CMP_T + t];
    __syncthreads();

    const float* x = tile + t * CC;   // stride 21: conflict-free (21 coprime 32)
    float xs[CC];
#pragma unroll
    for (int c = 0; c < CC; c++) xs[c] = x[c];

    // 3-way partial trees to break the 21-deep dependency chains
    float m0 = xs[0], m1 = xs[1], m2 = xs[2];
#pragma unroll
    for (int c = 3; c < CC; c += 3) {
        m0 = fmaxf(m0, xs[c]);
        if (c + 1 < CC) m1 = fmaxf(m1, xs[c + 1]);
        if (c + 2 < CC) m2 = fmaxf(m2, xs[c + 2]);
    }
    float m = fmaxf(m0, fmaxf(m1, m2));
    float s0 = 0.f, s1 = 0.f, s2 = 0.f;
#pragma unroll
    for (int c = 0; c < CC; c += 3) {
        s0 += __expf(xs[c] - m);
        if (c + 1 < CC) s1 += __expf(xs[c + 1] - m);
        if (c + 2 < CC) s2 += __expf(xs[c + 2] - m);
    }
    float lse = m + __logf(s0 + s1 + s2);

    float my_pos = 0.f;
    unsigned int my_n = 0u;
    float val = 0.f;
    if (p_raw != 0) {
        const float* g = gts + (size_t)i * CC;
        float dot = 0.f;
#pragma unroll
        for (int c = 0; c < CC; c++) dot += g[c] * xs[c];  // one-hot -> x[label]
        my_pos = lse - dot;
        my_n = 1u;
    } else {
        val = gbg * (lse - xs[CC - 1]);                    // >= 0
    }

    // warp-aggregated compaction of positive candidates + histograms
    unsigned int mask = __ballot_sync(0xffffffffu, val > 0.f);
    if (val > 0.f) {
        int lane = t & 31;
        int leader = __ffs(mask) - 1;
        unsigned int pre = mask & ((1u << lane) - 1u);
        int base;
        if (lane == leader) base = (int)atomicAdd(&g_ncand, (unsigned int)__popc(mask));
        base = __shfl_sync(mask, base, leader);
        g_cmp[base + __popc(pre)] = val;

        unsigned int b = __float_as_uint(val);
        atomicAdd(&g_hist1[b >> 16], 1u);
        atomicAdd(&g_chunk1[b >> 22], 1u);
    }

    // block reduce pos_sum / npos via shuffles
#pragma unroll
    for (int off = 16; off > 0; off >>= 1) {
        my_pos += __shfl_down_sync(0xffffffffu, my_pos, off);
        my_n   += __shfl_down_sync(0xffffffffu, my_n, off);
    }
    __shared__ float wf[8];
    __shared__ unsigned int wi[8];
    if ((t & 31) == 0) { wf[t >> 5] = my_pos; wi[t >> 5] = my_n; }
    __syncthreads();
    if (t < 32) {
        float v = (t < 8) ? wf[t] : 0.f;
        unsigned int n = (t < 8) ? wi[t] : 0u;
#pragma unroll
        for (int off = 4; off > 0; off >>= 1) {
            v += __shfl_down_sync(0xffffffffu, v, off);
            n += __shfl_down_sync(0xffffffffu, n, off);
        }
        if (t == 0) {
            if (v != 0.f) atomicAdd(&g_pos_sum, v);
            if (n != 0u)  atomicAdd(&g_npos, n);
        }
    }

    // last finishing block runs the level-1 select
    __threadfence();
    __shared__ unsigned int isLast;
    if (t == 0) isLast = (atomicAdd(&g_cnt1, 1u) == (unsigned int)gridDim.x - 1u) ? 1u : 0u;
    __syncthreads();
    if (isLast) {
        unsigned long long N = (unsigned long long)g_npos;
        unsigned long long k3 = 3ull * N;
        unsigned long long kn = (unsigned long long)BD - N;
        unsigned int k = (unsigned int)(k3 < kn ? k3 : kn);
        radix_scan_256(g_hist1, g_chunk1, k);
        if (t == 0) g_cnt1 = 0u;   // reset for next replay (all blocks arrived)
    }
}

// ---------------- single-block tail: hist2 + scan2 + negsum + finalize + scrub ----
// Operates on the compacted candidate array (~27k floats, L2-resident), then
// scrubs every global it and compute dirtied so the next replay starts clean.
__global__ void __launch_bounds__(1024) tail_kernel(float* __restrict__ out) {
    int t = threadIdx.x;
    int nc = (int)g_ncand;
    int T1 = g_T1;

    if (T1 >= 0) {
        // build low-16-bit histogram of the boundary bucket
        for (int j = t; j < nc; j += 1024) {
            unsigned int b = __float_as_uint(g_cmp[j]);
            if ((int)(b >> 16) == T1) {
                atomicAdd(&g_hist2[b & 0xffffu], 1u);
                atomicAdd(&g_chunk2[(b & 0xffffu) >> 6], 1u);
            }
        }
        __syncthreads();   // same-block: atomics (L2) visible to the scan's loads
        radix_scan_1024(g_hist2, g_chunk2, g_need1);
        __syncthreads();
    }

    unsigned int thr = g_thr_bits;   // 0 when T1 < 0 -> sum every candidate
    float local = 0.f;
#pragma unroll 4
    for (int j = t; j < nc; j += 1024) {
        float v = g_cmp[j];                      // all compacted values are > 0
        if (__float_as_uint(v) > thr) local += v;
    }
#pragma unroll
    for (int off = 16; off > 0; off >>= 1)
        local += __shfl_down_sync(0xffffffffu, local, off);
    __shared__ float wf[32];
    if ((t & 31) == 0) wf[t >> 5] = local;
    __syncthreads();
    if (t < 32) {
        float v = wf[t];
#pragma unroll
        for (int off = 16; off > 0; off >>= 1)
            v += __shfl_down_sync(0xffffffffu, v, off);
        if (t == 0) {
            float thrv = __uint_as_float(g_thr_bits);
            float neg = v + (float)g_rem * thrv;
            out[0] = (g_pos_sum + neg) / (float)g_npos;
        }
    }
    __syncthreads();   // out written (and all reads of scalars done) before scrub

    // ---- scrub: zero exactly the touched buckets, via the candidate list ----
    for (int j = t; j < nc; j += 1024) {
        unsigned int b = __float_as_uint(g_cmp[j]);
        g_hist1[b >> 16] = 0u;
        g_chunk1[b >> 22] = 0u;
        if ((int)(b >> 16) == T1) {
            g_hist2[b & 0xffffu] = 0u;
            g_chunk2[(b & 0xffffu) >> 6] = 0u;
        }
    }
    if (t == 0) {
        g_pos_sum = 0.f; g_npos = 0u; g_ncand = 0u;
        g_T1 = -1; g_need1 = 0u; g_thr_bits = 0u; g_rem = 0u;
    }
}

extern "C" void kernel_launch(void* const* d_in, const int* in_sizes, int n_in,
                              void* d_out, int out_size) {
    const float* pred = (const float*)d_in[0];
    const float* gts  = (const float*)d_in[1];
    const int*   pos  = (const int*)d_in[2];
    float* out = (float*)d_out;

    compute_kernel<<<CMP_G, CMP_T>>>(pred, gts, pos);
    tail_kernel<<<1, 1024>>>(out);
}